// round 13
// baseline (speedup 1.0000x reference)
#include <cuda_runtime.h>
#include <math.h>
#include <stdint.h>

// Problem constants
#define TOK   4096          // B*S
#define DDIM  768
#define HDIM  3072
#define NEXP  4
#define NLAY  2
#define BM    128
#define MAXROWS 4608        // TOK + NEXP*BM (segment padding)
#define MAXMT   36          // MAXROWS / BM

// ---------------- scratch (no allocations allowed) ----------------
__device__ float g_h[MAXROWS * DDIM];              // 13.6 MB
__device__ float g_act[(size_t)MAXROWS * HDIM];    // 56.6 MB
__device__ int   g_perm[MAXROWS];
__device__ int   g_counts[NEXP];
__device__ int   g_poff[NEXP + 1];
__device__ int   g_cursor[NEXP];

// ---------------- small helpers ----------------
__device__ __forceinline__ float gelu_f(float v) {
    return 0.5f * v * (1.0f + erff(v * 0.70710678118654752f));
}

__device__ __forceinline__ void cp16(uint32_t dst, const void* src) {
    asm volatile("cp.async.cg.shared.global [%0], [%1], 16;\n" :: "r"(dst), "l"(src));
}
#define CP_COMMIT() asm volatile("cp.async.commit_group;\n" ::: "memory")
#define CP_WAIT1()  asm volatile("cp.async.wait_group 1;\n" ::: "memory")

__device__ __forceinline__ void mma_tf32(float c[4], const uint32_t a[4], const uint32_t b[2]) {
    asm volatile(
        "mma.sync.aligned.m16n8k8.row.col.f32.tf32.tf32.f32 "
        "{%0,%1,%2,%3}, {%4,%5,%6,%7}, {%8,%9}, {%0,%1,%2,%3};\n"
        : "+f"(c[0]), "+f"(c[1]), "+f"(c[2]), "+f"(c[3])
        : "r"(a[0]), "r"(a[1]), "r"(a[2]), "r"(a[3]), "r"(b[0]), "r"(b[1]));
}

// ---------------- expert sort ----------------
__global__ void reset_kernel() {
    int i = blockIdx.x * blockDim.x + threadIdx.x;
    if (i < NEXP) g_counts[i] = 0;
    if (i < MAXROWS) g_perm[i] = -1;
}

__global__ void hist_kernel(const int* __restrict__ eidx) {
    int i = blockIdx.x * blockDim.x + threadIdx.x;
    if (i < TOK) atomicAdd(&g_counts[eidx[i]], 1);
}

__global__ void scan_kernel() {
    int off = 0;
    for (int e = 0; e < NEXP; e++) {
        g_poff[e] = off;
        g_cursor[e] = off;
        off += ((g_counts[e] + BM - 1) / BM) * BM;   // 128-align each segment
    }
    g_poff[NEXP] = off;
}

__global__ void assign_kernel(const int* __restrict__ eidx) {
    int i = blockIdx.x * blockDim.x + threadIdx.x;
    if (i < TOK) {
        int e = eidx[i];
        int p = atomicAdd(&g_cursor[e], 1);
        g_perm[p] = i;
    }
}

// ---------------- fused LayerNorm + gather into sorted order ----------------
__global__ void ln_gather_kernel(const float* __restrict__ xb,
                                 const float* __restrict__ gma,
                                 const float* __restrict__ bta) {
    int r = blockIdx.x;
    int tid = threadIdx.x;
    int t = g_perm[r];
    float* hrow = g_h + (size_t)r * DDIM;
    if (t < 0) {
        for (int i = tid; i < DDIM; i += 256) hrow[i] = 0.f;
        return;
    }
    const float* xr = xb + (size_t)t * DDIM;
    float s = 0.f, ss = 0.f;
    for (int i = tid; i < DDIM; i += 256) {
        float v = xr[i];
        s += v; ss += v * v;
    }
    #pragma unroll
    for (int o = 16; o; o >>= 1) {
        s  += __shfl_xor_sync(0xffffffffu, s,  o);
        ss += __shfl_xor_sync(0xffffffffu, ss, o);
    }
    __shared__ float ws[8], wss[8], smu, srstd;
    int wid = tid >> 5, lane = tid & 31;
    if (lane == 0) { ws[wid] = s; wss[wid] = ss; }
    __syncthreads();
    if (tid == 0) {
        float S1 = 0.f, S2 = 0.f;
        #pragma unroll
        for (int w = 0; w < 8; w++) { S1 += ws[w]; S2 += wss[w]; }
        float mu = S1 * (1.0f / DDIM);
        float var = S2 * (1.0f / DDIM) - mu * mu;
        smu = mu;
        srstd = rsqrtf(var + 1e-6f);
    }
    __syncthreads();
    float mu = smu, rstd = srstd;
    for (int i = tid; i < DDIM; i += 256)
        hrow[i] = (xr[i] - mu) * rstd * gma[i] + bta[i];
}

// ---------------- TF32 grouped GEMM, 128x128x16, 8 warps, cp.async x2 ----------------
// GELU=true : Out[row][N] = gelu(A@W + bias)          (A = g_h,  W = W1[l])
// GELU=false: x[perm[row]][N] += A@W + bias  (scatter) (A = g_act, W = W2[l])
template<int K, int N, bool GELU>
__global__ void __launch_bounds__(256) gemm_kernel(
    const float* __restrict__ A,
    const float* __restrict__ W,
    const float* __restrict__ bias,
    float* __restrict__ Out)
{
    const int BK = 16;
    int rowStart = blockIdx.y * BM;
    if (rowStart >= g_poff[NEXP]) return;
    int e = 3;
    if      (rowStart < g_poff[1]) e = 0;
    else if (rowStart < g_poff[2]) e = 1;
    else if (rowStart < g_poff[3]) e = 2;
    int colStart = blockIdx.x * 128;

    const float* Ab = A + (size_t)rowStart * K;
    const float* Wb = W + (size_t)e * K * N + colStart;

    __shared__ __align__(16) float As[2][128][20];   // [m][k], stride 20 -> conflict-free
    __shared__ __align__(16) float Bs[2][16][132];   // [k][n], stride 132 -> conflict-free

    int tid = threadIdx.x;

    auto load_stage = [&](int buf, int k0) {
        for (int c = tid; c < 512; c += 256) {       // A tile: 128 rows x 16 fp32
            int m = c >> 2, kq = (c & 3) << 2;
            uint32_t dst = (uint32_t)__cvta_generic_to_shared(&As[buf][m][kq]);
            cp16(dst, Ab + (size_t)m * K + k0 + kq);
        }
        for (int c = tid; c < 512; c += 256) {       // B tile: 16 rows x 128 fp32
            int k = c >> 5, nq = (c & 31) << 2;
            uint32_t dst = (uint32_t)__cvta_generic_to_shared(&Bs[buf][k][nq]);
            cp16(dst, Wb + (size_t)(k0 + k) * N + nq);
        }
    };

    load_stage(0, 0);  CP_COMMIT();
    load_stage(1, BK); CP_COMMIT();

    int warp = tid >> 5, lane = tid & 31;
    int wr = warp >> 1;      // 0..3 -> M offset wr*32
    int wc = warp & 1;       // 0..1 -> N offset wc*64
    int g = lane >> 2, tg = lane & 3;

    float acc[2][8][4];
    #pragma unroll
    for (int i = 0; i < 2; i++)
        #pragma unroll
        for (int j = 0; j < 8; j++)
            #pragma unroll
            for (int q = 0; q < 4; q++) acc[i][j][q] = 0.f;

    const int nK = K / BK;
    for (int kt = 0; kt < nK; ++kt) {
        CP_WAIT1();
        __syncthreads();
        int buf = kt & 1;
        #pragma unroll
        for (int ks = 0; ks < 16; ks += 8) {
            uint32_t a[2][4];
            #pragma unroll
            for (int i = 0; i < 2; i++) {
                int m0 = wr * 32 + i * 16;
                a[i][0] = __float_as_uint(As[buf][m0 + g    ][ks + tg    ]);
                a[i][1] = __float_as_uint(As[buf][m0 + g + 8][ks + tg    ]);
                a[i][2] = __float_as_uint(As[buf][m0 + g    ][ks + tg + 4]);
                a[i][3] = __float_as_uint(As[buf][m0 + g + 8][ks + tg + 4]);
            }
            uint32_t b[8][2];
            #pragma unroll
            for (int j = 0; j < 8; j++) {
                int n0 = wc * 64 + j * 8 + g;
                b[j][0] = __float_as_uint(Bs[buf][ks + tg    ][n0]);
                b[j][1] = __float_as_uint(Bs[buf][ks + tg + 4][n0]);
            }
            #pragma unroll
            for (int i = 0; i < 2; i++)
                #pragma unroll
                for (int j = 0; j < 8; j++)
                    mma_tf32(acc[i][j], a[i], b[j]);
        }
        __syncthreads();
        if (kt + 2 < nK) load_stage(buf, (kt + 2) * BK);
        CP_COMMIT();   // always commit (possibly empty) so wait_group 1 stays correct
    }

    // epilogue
    if (GELU) {
        #pragma unroll
        for (int i = 0; i < 2; i++) {
            int r0 = rowStart + wr * 32 + i * 16 + g;
            #pragma unroll
            for (int j = 0; j < 8; j++) {
                int col = colStart + wc * 64 + j * 8 + tg * 2;
                float b0v = bias[e * N + col], b1v = bias[e * N + col + 1];
                float* o0 = Out + (size_t)r0 * N + col;
                float* o1 = Out + (size_t)(r0 + 8) * N + col;
                o0[0] = gelu_f(acc[i][j][0] + b0v);
                o0[1] = gelu_f(acc[i][j][1] + b1v);
                o1[0] = gelu_f(acc[i][j][2] + b0v);
                o1[1] = gelu_f(acc[i][j][3] + b1v);
            }
        }
    } else {
        #pragma unroll
        for (int i = 0; i < 2; i++) {
            int r0 = rowStart + wr * 32 + i * 16 + g;
            int t0 = g_perm[r0], t1 = g_perm[r0 + 8];
            #pragma unroll
            for (int j = 0; j < 8; j++) {
                int col = colStart + wc * 64 + j * 8 + tg * 2;
                float b0v = bias[e * N + col], b1v = bias[e * N + col + 1];
                if (t0 >= 0) {
                    float* o = Out + (size_t)t0 * N + col;
                    o[0] += acc[i][j][0] + b0v;
                    o[1] += acc[i][j][1] + b1v;
                }
                if (t1 >= 0) {
                    float* o = Out + (size_t)t1 * N + col;
                    o[0] += acc[i][j][2] + b0v;
                    o[1] += acc[i][j][3] + b1v;
                }
            }
        }
    }
}

// ---------------- launch ----------------
extern "C" void kernel_launch(void* const* d_in, const int* in_sizes, int n_in,
                              void* d_out, int out_size) {
    (void)in_sizes; (void)n_in; (void)out_size;
    const float* x    = (const float*)d_in[0];
    const int*   eidx = (const int*)  d_in[1];
    const float* W1   = (const float*)d_in[2];
    const float* b1   = (const float*)d_in[3];
    const float* W2   = (const float*)d_in[4];
    const float* b2   = (const float*)d_in[5];
    const float* ln_g = (const float*)d_in[6];
    const float* ln_b = (const float*)d_in[7];
    float* xb = (float*)d_out;                 // mutable residual buffer == output

    void *ph = nullptr, *pa = nullptr;
    cudaGetSymbolAddress(&ph, g_h);
    cudaGetSymbolAddress(&pa, g_act);

    cudaMemcpyAsync(xb, x, (size_t)TOK * DDIM * sizeof(float),
                    cudaMemcpyDeviceToDevice, 0);

    reset_kernel <<<(MAXROWS + 255) / 256, 256>>>();
    hist_kernel  <<<(TOK + 255) / 256, 256>>>(eidx);
    scan_kernel  <<<1, 1>>>();
    assign_kernel<<<(TOK + 255) / 256, 256>>>(eidx);

    for (int l = 0; l < NLAY; ++l) {
        ln_gather_kernel<<<MAXROWS, 256>>>(xb, ln_g + (size_t)l * DDIM,
                                               ln_b + (size_t)l * DDIM);
        gemm_kernel<DDIM, HDIM, true><<<dim3(HDIM / 128, MAXMT), 256>>>(
            (const float*)ph,
            W1 + (size_t)l * NEXP * DDIM * HDIM,
            b1 + (size_t)l * NEXP * HDIM,
            (float*)pa);
        gemm_kernel<HDIM, DDIM, false><<<dim3(DDIM / 128, MAXMT), 256>>>(
            (const float*)pa,
            W2 + (size_t)l * NEXP * HDIM * DDIM,
            b2 + (size_t)l * NEXP * DDIM,
            xb);
    }
}

// round 17
// speedup vs baseline: 1.4834x; 1.4834x over previous
#include <cuda_runtime.h>
#include <math.h>
#include <stdint.h>

// Problem constants
#define TOK   4096          // B*S
#define DDIM  768
#define HDIM  3072
#define NEXP  4
#define BM    128
#define MAXROWS 4608        // TOK + NEXP*BM (segment padding)
#define MAXMT   36          // MAXROWS / BM

#if defined(__CUDA_ARCH_FEAT_SM103_ALL) || defined(__CUDA_ARCH_FEAT_SM100_ALL)
#define HAS_TCGEN05 1
#else
#define HAS_TCGEN05 0
#endif

// ---------------- scratch (no allocations allowed) ----------------
__device__ __align__(256) float g_h[MAXROWS * DDIM];              // 13.6 MB
__device__ __align__(256) float g_act[(size_t)MAXROWS * HDIM];    // 56.6 MB
__device__ int   g_perm[MAXROWS];
__device__ int   g_counts[NEXP];
__device__ int   g_poff[NEXP + 1];
__device__ int   g_cursor[NEXP];

// ---------------- helpers ----------------
__device__ __forceinline__ float gelu_f(float v) {
    return 0.5f * v * (1.0f + erff(v * 0.70710678118654752f));
}

__device__ __forceinline__ uint32_t smem_u32(const void* p) {
    uint32_t a;
    asm("{ .reg .u64 t; cvta.to.shared.u64 t, %1; cvt.u32.u64 %0, t; }" : "=r"(a) : "l"(p));
    return a;
}

__device__ __forceinline__ void cp16(uint32_t dst, const void* src) {
    asm volatile("cp.async.cg.shared.global [%0], [%1], 16;" :: "r"(dst), "l"(src));
}
#define CP_COMMIT() asm volatile("cp.async.commit_group;" ::: "memory")

__device__ __forceinline__ void mbar_init(uint32_t mbar, uint32_t cnt) {
    asm volatile("mbarrier.init.shared.b64 [%0], %1;" :: "r"(mbar), "r"(cnt) : "memory");
}
__device__ __forceinline__ void mbar_wait(uint32_t mbar, uint32_t parity) {
    asm volatile(
        "{\n\t.reg .pred P1;\n\t"
        "WL_%=:\n\t"
        "mbarrier.try_wait.parity.acquire.cta.shared::cta.b64 P1, [%0], %1, 0x989680;\n\t"
        "@P1 bra.uni WD_%=;\n\t"
        "bra.uni WL_%=;\n\t"
        "WD_%=:\n\t}"
        :: "r"(mbar), "r"(parity) : "memory");
}

// tcgen05 wrappers (cg1) — only referenced inside HAS_TCGEN05 code
#define TC_ALLOC(smem_addr, n) \
    asm volatile("tcgen05.alloc.cta_group::1.sync.aligned.shared::cta.b32 [%0], %1;" \
                 :: "r"(smem_addr), "r"((uint32_t)(n)) : "memory")
#define TC_RELINQ() \
    asm volatile("tcgen05.relinquish_alloc_permit.cta_group::1.sync.aligned;")
#define TC_DEALLOC(tmem, n) \
    asm volatile("tcgen05.dealloc.cta_group::1.sync.aligned.b32 %0, %1;" :: "r"(tmem), "r"((uint32_t)(n)))
#define TC_COMMIT(mbar) \
    asm volatile("tcgen05.commit.cta_group::1.mbarrier::arrive::one.shared::cluster.b64 [%0];" \
                 :: "r"(mbar) : "memory")
#define TC_FENCE_AFTER()  asm volatile("tcgen05.fence::after_thread_sync;" ::: "memory")
#define TC_FENCE_BEFORE() asm volatile("tcgen05.fence::before_thread_sync;" ::: "memory")
#define TC_WAIT_LD()      asm volatile("tcgen05.wait::ld.sync.aligned;" ::: "memory")
#define FENCE_ASYNC()     asm volatile("fence.proxy.async.shared::cta;" ::: "memory")

#define TC_MMA_TF32_SS(d_tmem, a_desc, b_desc, idesc, en) \
    asm volatile( \
        "{\n\t.reg .pred p;\n\t" \
        "setp.ne.u32 p, %5, 0;\n\t" \
        "tcgen05.mma.cta_group::1.kind::tf32 [%0], %1, %2, %3, {%4, %4, %4, %4}, p;\n\t}" \
        :: "r"(d_tmem), "l"(a_desc), "l"(b_desc), "r"(idesc), "r"(0u), "r"((uint32_t)(en)) \
        : "memory")

#define TC_LD_X32(r, tmem_addr) \
    asm volatile( \
        "tcgen05.ld.sync.aligned.32x32b.x32.b32 " \
        "{%0, %1, %2, %3, %4, %5, %6, %7, " \
        " %8, %9, %10, %11, %12, %13, %14, %15, " \
        " %16, %17, %18, %19, %20, %21, %22, %23, " \
        " %24, %25, %26, %27, %28, %29, %30, %31}, [%32];" \
        : "=r"((r)[0]),  "=r"((r)[1]),  "=r"((r)[2]),  "=r"((r)[3]), \
          "=r"((r)[4]),  "=r"((r)[5]),  "=r"((r)[6]),  "=r"((r)[7]), \
          "=r"((r)[8]),  "=r"((r)[9]),  "=r"((r)[10]), "=r"((r)[11]), \
          "=r"((r)[12]), "=r"((r)[13]), "=r"((r)[14]), "=r"((r)[15]), \
          "=r"((r)[16]), "=r"((r)[17]), "=r"((r)[18]), "=r"((r)[19]), \
          "=r"((r)[20]), "=r"((r)[21]), "=r"((r)[22]), "=r"((r)[23]), \
          "=r"((r)[24]), "=r"((r)[25]), "=r"((r)[26]), "=r"((r)[27]), \
          "=r"((r)[28]), "=r"((r)[29]), "=r"((r)[30]), "=r"((r)[31]) \
        : "r"(tmem_addr))

// SW128 K-major SMEM descriptor base: layout=SW128(2), version=1(Blackwell), SBO=64, LBO=1
static constexpr uint64_t DESC_BASE =
    (2ull << 61) | (1ull << 46) | (64ull << 32) | (1ull << 16);

// idesc for kind::tf32, cg1: F32 accum(1<<4), atype=TF32(2<<7), btype=TF32(2<<10),
// N=128 -> 16<<17, M=128 -> 8<<24
static constexpr uint32_t IDESC_TF32 =
    (1u << 4) | (2u << 7) | (2u << 10) | ((128u / 8) << 17) | ((128u / 16) << 24);

// fallback warp-mma
__device__ __forceinline__ void mma_sync_tf32(float c[4], const uint32_t a[4], const uint32_t b[2]) {
    asm volatile(
        "mma.sync.aligned.m16n8k8.row.col.f32.tf32.tf32.f32 "
        "{%0,%1,%2,%3}, {%4,%5,%6,%7}, {%8,%9}, {%0,%1,%2,%3};\n"
        : "+f"(c[0]), "+f"(c[1]), "+f"(c[2]), "+f"(c[3])
        : "r"(a[0]), "r"(a[1]), "r"(a[2]), "r"(a[3]), "r"(b[0]), "r"(b[1]));
}

// ---------------- expert sort ----------------
__global__ void reset_kernel() {
    int i = blockIdx.x * blockDim.x + threadIdx.x;
    if (i < NEXP) g_counts[i] = 0;
    if (i < MAXROWS) g_perm[i] = -1;
}
__global__ void hist_kernel(const int* __restrict__ eidx) {
    int i = blockIdx.x * blockDim.x + threadIdx.x;
    if (i < TOK) atomicAdd(&g_counts[eidx[i]], 1);
}
__global__ void scan_kernel() {
    int off = 0;
    for (int e = 0; e < NEXP; e++) {
        g_poff[e] = off;
        g_cursor[e] = off;
        off += ((g_counts[e] + BM - 1) / BM) * BM;
    }
    g_poff[NEXP] = off;
}
__global__ void assign_kernel(const int* __restrict__ eidx) {
    int i = blockIdx.x * blockDim.x + threadIdx.x;
    if (i < TOK) {
        int e = eidx[i];
        int p = atomicAdd(&g_cursor[e], 1);
        g_perm[p] = i;
    }
}

// ---------------- fused LayerNorm + gather into sorted order ----------------
__global__ void ln_gather_kernel(const float* __restrict__ xb,
                                 const float* __restrict__ gma,
                                 const float* __restrict__ bta) {
    int r = blockIdx.x;
    int tid = threadIdx.x;
    int t = g_perm[r];
    float* hrow = g_h + (size_t)r * DDIM;
    if (t < 0) {
        for (int i = tid; i < DDIM; i += 256) hrow[i] = 0.f;
        return;
    }
    const float* xr = xb + (size_t)t * DDIM;
    float s = 0.f, ss = 0.f;
    for (int i = tid; i < DDIM; i += 256) {
        float v = xr[i];
        s += v; ss += v * v;
    }
    #pragma unroll
    for (int o = 16; o; o >>= 1) {
        s  += __shfl_xor_sync(0xffffffffu, s,  o);
        ss += __shfl_xor_sync(0xffffffffu, ss, o);
    }
    __shared__ float ws[8], wss[8], smu, srstd;
    int wid = tid >> 5, lane = tid & 31;
    if (lane == 0) { ws[wid] = s; wss[wid] = ss; }
    __syncthreads();
    if (tid == 0) {
        float S1 = 0.f, S2 = 0.f;
        #pragma unroll
        for (int w = 0; w < 8; w++) { S1 += ws[w]; S2 += wss[w]; }
        float mu = S1 * (1.0f / DDIM);
        float var = S2 * (1.0f / DDIM) - mu * mu;
        smu = mu; srstd = rsqrtf(var + 1e-6f);
    }
    __syncthreads();
    float mu = smu, rstd = srstd;
    for (int i = tid; i < DDIM; i += 256)
        hrow[i] = (xr[i] - mu) * rstd * gma[i] + bta[i];
}

// ---------------- grouped GEMM, 128x128 tile ----------------
// D[128 rows, 128 cols] = A(rows K-major) @ W^T slice   (per-expert weights)
// GELU=true : Out[r][colStart+c] = gelu(D + bias)
// GELU=false: Out[g_perm[r]][colStart+c] += D + bias  (residual scatter)
#define DSMEM_BYTES 66624

template<int K, int N_TOTAL, bool GELU>
__global__ void __launch_bounds__(256) mma_gemm(
    const float* __restrict__ A,
    const float* __restrict__ W,
    const float* __restrict__ bias,
    float* __restrict__ Out)
{
    int rowStart = blockIdx.y * BM;
    if (rowStart >= g_poff[NEXP]) return;
    int e = 3;
    if      (rowStart < g_poff[1]) e = 0;
    else if (rowStart < g_poff[2]) e = 1;
    else if (rowStart < g_poff[3]) e = 2;
    int colStart = blockIdx.x * 128;

    extern __shared__ char dsm[];
    int tid  = threadIdx.x;
    int warp = tid >> 5, lane = tid & 31;

    const float* Ab = A + (size_t)rowStart * K;
    const float* Wb = W + (size_t)e * K * N_TOTAL + colStart;

#if HAS_TCGEN05
    // ================= tcgen05 path (sm_103a) =================
    uint32_t sb    = smem_u32(dsm);
    uint32_t ctrl  = sb;                          // [0]=tmem ptr, [8],[16]=mbars
    uint32_t tiles = (sb + 64 + 1023) & ~1023u;   // 1024-aligned for SW128 desc
    // A tile buf b: tiles + b*16384 ; B tile buf b: tiles + 32768 + b*16384

    if (warp == 0) { TC_ALLOC(ctrl, 128); TC_RELINQ(); }
    if (tid == 0)  { mbar_init(ctrl + 8, 1); mbar_init(ctrl + 16, 1); }
    __syncthreads();
    uint32_t tmem;
    asm volatile("ld.shared.b32 %0, [%1];" : "=r"(tmem) : "r"(ctrl));

    // per-thread load roles (256 threads)
    const int arow = tid >> 1, ah = tid & 1;            // A: 2 threads per row
    const uint32_t aswz = (uint32_t)(arow & 7) << 4;
    const int bn = tid & 127, bkh = tid >> 7;           // B: 2 threads per n-column
    const uint32_t bswz = (uint32_t)(bn & 7) << 4;

    auto loadStage = [&](int buf, int k0) {
        // A: 128 rows x 32 fp32 (128B rows, SW128)
        {
            uint32_t abase = tiles + buf * 16384 + (uint32_t)arow * 128;
            const float* asrc = Ab + (size_t)arow * K + k0 + ah * 16;
            #pragma unroll
            for (int ci = 0; ci < 4; ci++)
                cp16(abase + (((uint32_t)(ah * 64 + ci * 16)) ^ aswz), asrc + ci * 4);
        }
        // B: transpose W[k0..k0+31][colStart+bn] -> row bn, k-floats [bkh*16, +16)
        {
            float r[16];
            const float* ws = Wb + (size_t)(k0 + bkh * 16) * N_TOTAL + bn;
            #pragma unroll
            for (int j = 0; j < 16; j++)
                r[j] = ws[(size_t)j * N_TOTAL];
            uint32_t bbase = tiles + 32768 + buf * 16384 + (uint32_t)bn * 128;
            #pragma unroll
            for (int q = 0; q < 4; q++) {
                uint32_t a = bbase + (((uint32_t)(bkh * 64 + q * 16)) ^ bswz);
                asm volatile("st.shared.v4.f32 [%0], {%1,%2,%3,%4};"
                             :: "r"(a), "f"(r[4*q]), "f"(r[4*q+1]), "f"(r[4*q+2]), "f"(r[4*q+3]));
            }
        }
    };

    constexpr int nK = K / 32;

    loadStage(0, 0);
    CP_COMMIT();

    for (int kt = 0; kt < nK; kt++) {
        int buf = kt & 1;
        if (kt + 1 < nK) {
            if (kt >= 1) mbar_wait(ctrl + 8 + 8 * ((kt - 1) & 1), ((kt - 1) >> 1) & 1);
            loadStage(buf ^ 1, (kt + 1) * 32);
            CP_COMMIT();
            asm volatile("cp.async.wait_group 1;" ::: "memory");
        } else {
            asm volatile("cp.async.wait_group 0;" ::: "memory");
        }
        FENCE_ASYNC();
        __syncthreads();
        if (tid == 0) {
            uint64_t ad = DESC_BASE | ((uint64_t)((tiles + buf * 16384) >> 4) & 0x3FFF);
            uint64_t bd = DESC_BASE | ((uint64_t)((tiles + 32768 + buf * 16384) >> 4) & 0x3FFF);
            #pragma unroll
            for (int s2 = 0; s2 < 4; s2++)   // 4 x K=8 steps per 32-K chunk, +32B each
                TC_MMA_TF32_SS(tmem, ad + s2 * 2, bd + s2 * 2, IDESC_TF32,
                               (kt > 0) || (s2 > 0));
            TC_COMMIT(ctrl + 8 + 8 * buf);
        }
    }

    mbar_wait(ctrl + 8 + 8 * ((nK - 1) & 1), ((nK - 1) >> 1) & 1);
    TC_FENCE_AFTER();

    // epilogue: warp w reads subpartition (w&3) rows; warps 0-3 cols 0-63, 4-7 cols 64-127
    int r = rowStart + (warp & 3) * 32 + lane;
    int ccb = (warp >> 2) * 2;
    if (GELU) {
        #pragma unroll
        for (int c2 = 0; c2 < 2; c2++) {
            int cc = ccb + c2;
            uint32_t d[32];
            TC_LD_X32(d, tmem + cc * 32);
            TC_WAIT_LD();
            int c0 = colStart + cc * 32;
            float* orow = Out + (size_t)r * N_TOTAL + c0;
            const float* brow = bias + (size_t)e * N_TOTAL + c0;
            #pragma unroll
            for (int j = 0; j < 32; j += 4) {
                float4 v;
                v.x = gelu_f(__uint_as_float(d[j    ]) + brow[j    ]);
                v.y = gelu_f(__uint_as_float(d[j + 1]) + brow[j + 1]);
                v.z = gelu_f(__uint_as_float(d[j + 2]) + brow[j + 2]);
                v.w = gelu_f(__uint_as_float(d[j + 3]) + brow[j + 3]);
                *reinterpret_cast<float4*>(orow + j) = v;
            }
        }
    } else {
        int t0 = g_perm[r];
        #pragma unroll
        for (int c2 = 0; c2 < 2; c2++) {
            int cc = ccb + c2;
            uint32_t d[32];
            TC_LD_X32(d, tmem + cc * 32);   // warp-collective
            TC_WAIT_LD();
            if (t0 >= 0) {
                int c0 = colStart + cc * 32;
                float* orow = Out + (size_t)t0 * N_TOTAL + c0;
                const float* brow = bias + (size_t)e * N_TOTAL + c0;
                #pragma unroll
                for (int j = 0; j < 32; j += 4) {
                    float4 cur = *reinterpret_cast<float4*>(orow + j);
                    cur.x += __uint_as_float(d[j    ]) + brow[j    ];
                    cur.y += __uint_as_float(d[j + 1]) + brow[j + 1];
                    cur.z += __uint_as_float(d[j + 2]) + brow[j + 2];
                    cur.w += __uint_as_float(d[j + 3]) + brow[j + 3];
                    *reinterpret_cast<float4*>(orow + j) = cur;
                }
            }
        }
    }
    TC_FENCE_BEFORE();
    __syncthreads();
    if (warp == 0) TC_DEALLOC(tmem, 128);

#else
    // ================= fallback: mma.sync tf32 (proven R13 path) =================
    const int BK = 16;
    float* As = (float*)dsm;              // [2][128][20]
    float* Bs = (float*)dsm + 2*128*20;   // [2][16][132]
    #define ASF(b,m,k) As[((b)*128 + (m))*20 + (k)]
    #define BSF(b,k,n) Bs[((b)*16 + (k))*132 + (n)]

    auto load_stage = [&](int buf, int k0) {
        for (int c = tid; c < 512; c += 256) {       // A tile: 128 x 16 fp32
            int m = c >> 2, kq = (c & 3) << 2;
            uint32_t dst = smem_u32(&ASF(buf, m, kq));
            cp16(dst, Ab + (size_t)m * K + k0 + kq);
        }
        for (int c = tid; c < 512; c += 256) {       // B tile: 16 x 128 fp32
            int k = c >> 5, nq = (c & 31) << 2;
            uint32_t dst = smem_u32(&BSF(buf, k, nq));
            cp16(dst, Wb + (size_t)(k0 + k) * N_TOTAL + nq);
        }
    };

    load_stage(0, 0);  CP_COMMIT();
    load_stage(1, BK); CP_COMMIT();

    int wr = warp >> 1, wc = warp & 1;
    int g = lane >> 2, tg = lane & 3;

    float acc[2][8][4];
    #pragma unroll
    for (int i = 0; i < 2; i++)
        #pragma unroll
        for (int j = 0; j < 8; j++)
            #pragma unroll
            for (int q = 0; q < 4; q++) acc[i][j][q] = 0.f;

    const int nK = K / BK;
    for (int kt = 0; kt < nK; ++kt) {
        asm volatile("cp.async.wait_group 1;" ::: "memory");
        __syncthreads();
        int buf = kt & 1;
        #pragma unroll
        for (int ks = 0; ks < 16; ks += 8) {
            uint32_t a[2][4];
            #pragma unroll
            for (int i = 0; i < 2; i++) {
                int m0 = wr * 32 + i * 16;
                a[i][0] = __float_as_uint(ASF(buf, m0 + g,     ks + tg));
                a[i][1] = __float_as_uint(ASF(buf, m0 + g + 8, ks + tg));
                a[i][2] = __float_as_uint(ASF(buf, m0 + g,     ks + tg + 4));
                a[i][3] = __float_as_uint(ASF(buf, m0 + g + 8, ks + tg + 4));
            }
            uint32_t b[8][2];
            #pragma unroll
            for (int j = 0; j < 8; j++) {
                int n0 = wc * 64 + j * 8 + g;
                b[j][0] = __float_as_uint(BSF(buf, ks + tg,     n0));
                b[j][1] = __float_as_uint(BSF(buf, ks + tg + 4, n0));
            }
            #pragma unroll
            for (int i = 0; i < 2; i++)
                #pragma unroll
                for (int j = 0; j < 8; j++)
                    mma_sync_tf32(acc[i][j], a[i], b[j]);
        }
        __syncthreads();
        if (kt + 2 < nK) load_stage(buf, (kt + 2) * BK);
        CP_COMMIT();
    }

    if (GELU) {
        #pragma unroll
        for (int i = 0; i < 2; i++) {
            int r0 = rowStart + wr * 32 + i * 16 + g;
            #pragma unroll
            for (int j = 0; j < 8; j++) {
                int col = colStart + wc * 64 + j * 8 + tg * 2;
                float b0v = bias[e * N_TOTAL + col], b1v = bias[e * N_TOTAL + col + 1];
                float* o0 = Out + (size_t)r0 * N_TOTAL + col;
                float* o1 = Out + (size_t)(r0 + 8) * N_TOTAL + col;
                o0[0] = gelu_f(acc[i][j][0] + b0v);
                o0[1] = gelu_f(acc[i][j][1] + b1v);
                o1[0] = gelu_f(acc[i][j][2] + b0v);
                o1[1] = gelu_f(acc[i][j][3] + b1v);
            }
        }
    } else {
        #pragma unroll
        for (int i = 0; i < 2; i++) {
            int r0 = rowStart + wr * 32 + i * 16 + g;
            int t0 = g_perm[r0], t1 = g_perm[r0 + 8];
            #pragma unroll
            for (int j = 0; j < 8; j++) {
                int col = colStart + wc * 64 + j * 8 + tg * 2;
                float b0v = bias[e * N_TOTAL + col], b1v = bias[e * N_TOTAL + col + 1];
                if (t0 >= 0) {
                    float* o = Out + (size_t)t0 * N_TOTAL + col;
                    o[0] += acc[i][j][0] + b0v;
                    o[1] += acc[i][j][1] + b1v;
                }
                if (t1 >= 0) {
                    float* o = Out + (size_t)t1 * N_TOTAL + col;
                    o[0] += acc[i][j][2] + b0v;
                    o[1] += acc[i][j][3] + b1v;
                }
            }
        }
    }
    #undef ASF
    #undef BSF
#endif
}

// ---------------- launch ----------------
extern "C" void kernel_launch(void* const* d_in, const int* in_sizes, int n_in,
                              void* d_out, int out_size) {
    (void)in_sizes; (void)n_in; (void)out_size;
    const float* x    = (const float*)d_in[0];
    const int*   eidx = (const int*)  d_in[1];
    const float* W1   = (const float*)d_in[2];
    const float* b1   = (const float*)d_in[3];
    const float* W2   = (const float*)d_in[4];
    const float* b2   = (const float*)d_in[5];
    const float* ln_g = (const float*)d_in[6];
    const float* ln_b = (const float*)d_in[7];
    float* xb = (float*)d_out;                 // mutable residual buffer == output

    void *ph = nullptr, *pa = nullptr;
    cudaGetSymbolAddress(&ph, g_h);
    cudaGetSymbolAddress(&pa, g_act);

    cudaFuncSetAttribute(mma_gemm<DDIM, HDIM, true>,
                         cudaFuncAttributeMaxDynamicSharedMemorySize, DSMEM_BYTES);
    cudaFuncSetAttribute(mma_gemm<HDIM, DDIM, false>,
                         cudaFuncAttributeMaxDynamicSharedMemorySize, DSMEM_BYTES);

    cudaMemcpyAsync(xb, x, (size_t)TOK * DDIM * sizeof(float),
                    cudaMemcpyDeviceToDevice, 0);

    reset_kernel <<<(MAXROWS + 255) / 256, 256>>>();
    hist_kernel  <<<(TOK + 255) / 256, 256>>>(eidx);
    scan_kernel  <<<1, 1>>>();
    assign_kernel<<<(TOK + 255) / 256, 256>>>(eidx);

    for (int l = 0; l < 2; ++l) {
        ln_gather_kernel<<<MAXROWS, 256>>>(xb, ln_g + (size_t)l * DDIM,
                                               ln_b + (size_t)l * DDIM);
        mma_gemm<DDIM, HDIM, true><<<dim3(HDIM / 128, MAXMT), 256, DSMEM_BYTES>>>(
            (const float*)ph,
            W1 + (size_t)l * NEXP * DDIM * HDIM,
            b1 + (size_t)l * NEXP * HDIM,
            (float*)pa);
        mma_gemm<HDIM, DDIM, false><<<dim3(DDIM / 128, MAXMT), 256, DSMEM_BYTES>>>(
            (const float*)pa,
            W2 + (size_t)l * NEXP * HDIM * DDIM,
            b2 + (size_t)l * NEXP * DDIM,
            xb);
    }
}